// round 1
// baseline (speedup 1.0000x reference)
#include <cuda_runtime.h>
#include <math.h>

// Problem constants (fixed by the dataset)
constexpr int NB = 4;      // batch
constexpr int TS = 2048;   // tokens
constexpr int ED = 1024;   // embed

// Scratch (device globals; cudaMalloc is forbidden)
__device__ float g_q[(size_t)NB * TS * ED];
__device__ float g_k[(size_t)NB * TS * ED];
__device__ float g_v[(size_t)NB * TS * ED];
__device__ float g_w[(size_t)NB * TS * TS];

// ---------------------------------------------------------------------------
// Tiled SGEMM: C[M,N] = A[M,K] * op(B) (+ bias), all row-major.
//   TRANS_B = false : B is [K,N]  (ldb = N)
//   TRANS_B = true  : B is [N,K]  (ldb = K), computes A * B^T
// Block tile 128x128, K-tile 8, 256 threads, 8x8 per-thread microtile.
// All dims are multiples of 128/8 for this problem -> no bounds checks.
// ---------------------------------------------------------------------------
constexpr int TM = 128;
constexpr int TKB = 8;
constexpr int SPAD = 4;   // smem row padding (4*(128+4)=528B, 528%32=16 -> no conflict)

template <bool TRANS_B, bool HAS_BIAS>
__global__ __launch_bounds__(256, 2) void sgemm_kernel(
    const float* __restrict__ A,
    const float* __restrict__ B,
    const float* __restrict__ bias,
    float* __restrict__ C,
    int M, int N, int K,
    long strideA, long strideB, long strideC)
{
    __shared__ float As[TKB][TM + SPAD];
    __shared__ float Bs[TKB][TM + SPAD];

    const int batch = blockIdx.z;
    A += (long)batch * strideA;
    B += (long)batch * strideB;
    C += (long)batch * strideC;

    const int bm = blockIdx.y * TM;
    const int bn = blockIdx.x * TM;

    const int t  = threadIdx.x;
    const int tx = t & 15;         // 0..15
    const int ty = t >> 4;         // 0..15
    const int row0 = ty * 8;
    const int col0 = tx * 8;

    // A-tile loader: 128 rows x 8 cols, one float4 per thread (transposed store)
    const int la_r = t >> 1;          // 0..127
    const int la_s = (t & 1) * 4;     // 0 or 4

    // B-tile loader (no-trans): 8 rows x 128 cols, one float4 per thread
    const int lb_r = t >> 5;          // 0..7
    const int lb_c = (t & 31) * 4;    // 0..124

    float acc[8][8] = {};

    for (int k0 = 0; k0 < K; k0 += TKB) {
        // Load A tile (lda = K for every GEMM in this pipeline)
        {
            float4 a4 = *reinterpret_cast<const float4*>(
                A + (long)(bm + la_r) * K + (k0 + la_s));
            As[la_s + 0][la_r] = a4.x;
            As[la_s + 1][la_r] = a4.y;
            As[la_s + 2][la_r] = a4.z;
            As[la_s + 3][la_r] = a4.w;
        }
        // Load B tile
        if (TRANS_B) {
            // B is [N,K] row-major (ldb = K); need Bs[kk][n]
            float4 b4 = *reinterpret_cast<const float4*>(
                B + (long)(bn + la_r) * K + (k0 + la_s));
            Bs[la_s + 0][la_r] = b4.x;
            Bs[la_s + 1][la_r] = b4.y;
            Bs[la_s + 2][la_r] = b4.z;
            Bs[la_s + 3][la_r] = b4.w;
        } else {
            // B is [K,N] row-major (ldb = N)
            float4 b4 = *reinterpret_cast<const float4*>(
                B + (long)(k0 + lb_r) * N + (bn + lb_c));
            *reinterpret_cast<float4*>(&Bs[lb_r][lb_c]) = b4;
        }
        __syncthreads();

#pragma unroll
        for (int kk = 0; kk < TKB; kk++) {
            float4 a0 = *reinterpret_cast<const float4*>(&As[kk][row0]);
            float4 a1 = *reinterpret_cast<const float4*>(&As[kk][row0 + 4]);
            float4 b0 = *reinterpret_cast<const float4*>(&Bs[kk][col0]);
            float4 b1 = *reinterpret_cast<const float4*>(&Bs[kk][col0 + 4]);
            float ra[8] = {a0.x, a0.y, a0.z, a0.w, a1.x, a1.y, a1.z, a1.w};
            float rb[8] = {b0.x, b0.y, b0.z, b0.w, b1.x, b1.y, b1.z, b1.w};
#pragma unroll
            for (int i = 0; i < 8; i++)
#pragma unroll
                for (int j = 0; j < 8; j++)
                    acc[i][j] = fmaf(ra[i], rb[j], acc[i][j]);
        }
        __syncthreads();
    }

    // Epilogue: optional bias, vectorized stores
    float bvals[8];
    if (HAS_BIAS) {
#pragma unroll
        for (int j = 0; j < 8; j++) bvals[j] = bias[bn + col0 + j];
    }
#pragma unroll
    for (int i = 0; i < 8; i++) {
        float4 o0, o1;
        if (HAS_BIAS) {
            o0.x = acc[i][0] + bvals[0]; o0.y = acc[i][1] + bvals[1];
            o0.z = acc[i][2] + bvals[2]; o0.w = acc[i][3] + bvals[3];
            o1.x = acc[i][4] + bvals[4]; o1.y = acc[i][5] + bvals[5];
            o1.z = acc[i][6] + bvals[6]; o1.w = acc[i][7] + bvals[7];
        } else {
            o0.x = acc[i][0]; o0.y = acc[i][1]; o0.z = acc[i][2]; o0.w = acc[i][3];
            o1.x = acc[i][4]; o1.y = acc[i][5]; o1.z = acc[i][6]; o1.w = acc[i][7];
        }
        float* cp = C + (long)(bm + row0 + i) * N + (bn + col0);
        *reinterpret_cast<float4*>(cp)     = o0;
        *reinterpret_cast<float4*>(cp + 4) = o1;
    }
}

// ---------------------------------------------------------------------------
// Row softmax over rows of length TS=2048. One block (256 threads) per row.
// ---------------------------------------------------------------------------
__global__ __launch_bounds__(256) void softmax_rows_kernel(float* __restrict__ W)
{
    constexpr int PER = TS / 256;  // 8
    float* p = W + (long)blockIdx.x * TS;
    const int t = threadIdx.x;

    float v[PER];
    float mx = -INFINITY;
#pragma unroll
    for (int i = 0; i < PER; i++) {
        v[i] = p[t + i * 256];
        mx = fmaxf(mx, v[i]);
    }
    // warp reduce max
#pragma unroll
    for (int o = 16; o > 0; o >>= 1)
        mx = fmaxf(mx, __shfl_xor_sync(0xffffffffu, mx, o));

    __shared__ float smax[8];
    __shared__ float ssum[8];
    if ((t & 31) == 0) smax[t >> 5] = mx;
    __syncthreads();
    float bmx = smax[0];
#pragma unroll
    for (int i = 1; i < 8; i++) bmx = fmaxf(bmx, smax[i]);

    float sum = 0.f;
#pragma unroll
    for (int i = 0; i < PER; i++) {
        v[i] = __expf(v[i] - bmx);
        sum += v[i];
    }
#pragma unroll
    for (int o = 16; o > 0; o >>= 1)
        sum += __shfl_xor_sync(0xffffffffu, sum, o);
    if ((t & 31) == 0) ssum[t >> 5] = sum;
    __syncthreads();
    float bsum = 0.f;
#pragma unroll
    for (int i = 0; i < 8; i++) bsum += ssum[i];

    const float inv = 1.0f / bsum;
#pragma unroll
    for (int i = 0; i < PER; i++)
        p[t + i * 256] = v[i] * inv;
}

// ---------------------------------------------------------------------------
// Launch
// ---------------------------------------------------------------------------
extern "C" void kernel_launch(void* const* d_in, const int* in_sizes, int n_in,
                              void* d_out, int out_size)
{
    const float* X  = (const float*)d_in[0];
    const float* Wq = (const float*)d_in[1];
    const float* bq = (const float*)d_in[2];
    const float* Wk = (const float*)d_in[3];
    const float* bk = (const float*)d_in[4];
    const float* Wv = (const float*)d_in[5];
    const float* bv = (const float*)d_in[6];
    float* out = (float*)d_out;

    float *q, *k, *v, *w;
    cudaGetSymbolAddress((void**)&q, g_q);
    cudaGetSymbolAddress((void**)&k, g_k);
    cudaGetSymbolAddress((void**)&v, g_v);
    cudaGetSymbolAddress((void**)&w, g_w);

    const int M = NB * TS;  // 8192

    // 1) QKV projections: [8192,1024] @ [1024,1024] + bias
    {
        dim3 grid(ED / TM, M / TM, 1);
        sgemm_kernel<false, true><<<grid, 256>>>(X, Wq, bq, q, M, ED, ED, 0, 0, 0);
        sgemm_kernel<false, true><<<grid, 256>>>(X, Wk, bk, k, M, ED, ED, 0, 0, 0);
        sgemm_kernel<false, true><<<grid, 256>>>(X, Wv, bv, v, M, ED, ED, 0, 0, 0);
    }

    // 2) sim = q @ k^T per batch: [2048,1024] x [2048,1024]^T -> [2048,2048]
    {
        dim3 grid(TS / TM, TS / TM, NB);
        sgemm_kernel<true, false><<<grid, 256>>>(
            q, k, nullptr, w, TS, TS, ED,
            (long)TS * ED, (long)TS * ED, (long)TS * TS);
    }

    // 3) softmax rows
    softmax_rows_kernel<<<NB * TS, 256>>>(w);

    // 4) out = w @ v per batch: [2048,2048] x [2048,1024] -> [2048,1024]
    {
        dim3 grid(ED / TM, TS / TM, NB);
        sgemm_kernel<false, false><<<grid, 256>>>(
            w, v, nullptr, out, TS, ED, TS,
            (long)TS * TS, (long)TS * ED, (long)TS * ED);
    }
}